// round 1
// baseline (speedup 1.0000x reference)
#include <cuda_runtime.h>
#include <cstdint>

#define T_STEPS 128
#define B_TOT   8192
#define H_DIM   256
#define TILE_B  8
#define NTH     256
#define TAIL0   118   // first of the last 10 steps

typedef unsigned long long u64;

// ---- packed f32x2 helpers (Blackwell; ptxas never emits these from C++) ----
__device__ __forceinline__ u64 pk2(float lo, float hi) {
    u64 r; asm("mov.b64 %0, {%1, %2};" : "=l"(r) : "f"(lo), "f"(hi)); return r;
}
__device__ __forceinline__ void unpk2(u64 v, float& lo, float& hi) {
    asm("mov.b64 {%0, %1}, %2;" : "=f"(lo), "=f"(hi) : "l"(v));
}
__device__ __forceinline__ u64 fma2(u64 a, u64 b, u64 c) {
    u64 d; asm("fma.rn.f32x2 %0, %1, %2, %3;" : "=l"(d) : "l"(a), "l"(b), "l"(c)); return d;
}
__device__ __forceinline__ u64 mul2(u64 a, u64 b) {
    u64 d; asm("mul.rn.f32x2 %0, %1, %2;" : "=l"(d) : "l"(a), "l"(b)); return d;
}
__device__ __forceinline__ u64 add2(u64 a, u64 b) {
    u64 d; asm("add.rn.f32x2 %0, %1, %2;" : "=l"(d) : "l"(a), "l"(b)); return d;
}
// per-half: (m > 1.0f) ? 1.0f : 0.0f
__device__ __forceinline__ u64 gt1_2(u64 m) {
    u64 r;
    asm("{\n\t"
        ".reg .f32 plo, phi, rl, rh;\n\t"
        "mov.b64 {plo, phi}, %1;\n\t"
        "set.gt.f32.f32 rl, plo, 0f3F800000;\n\t"
        "set.gt.f32.f32 rh, phi, 0f3F800000;\n\t"
        "mov.b64 %0, {rl, rh};\n\t"
        "}" : "=l"(r) : "l"(m));
    return r;
}

__global__ void __launch_bounds__(NTH)
snn_fused_kernel(const float2* __restrict__ x2,   // [T, B] pairs (x0, x1)
                 const float2* __restrict__ w1p,  // [H] pairs (W1[h][0], W1[h][1])
                 const float*  __restrict__ w2,   // [2, 256]
                 float* __restrict__ out)         // [B, 2]
{
    __shared__ __align__(16) float sx0[T_STEPS][TILE_B];
    __shared__ __align__(16) float sx1[T_STEPS][TILE_B];
    __shared__ float sspk[TILE_B][H_DIM];

    const int tid = threadIdx.x;
    const int b0  = blockIdx.x * TILE_B;

    // --- stage x tile into shared (planar x0 / x1 for packed loads) ---
    #pragma unroll
    for (int i = 0; i < (T_STEPS * TILE_B) / NTH; ++i) {
        int idx = tid + i * NTH;
        int t = idx >> 3, bl = idx & 7;
        float2 v = x2[(size_t)t * B_TOT + b0 + bl];
        sx0[t][bl] = v.x;
        sx1[t][bl] = v.y;
    }

    const float2 w  = w1p[tid];
    const u64 w0d   = pk2(w.x, w.x);
    const u64 w1d   = pk2(w.y, w.y);
    const u64 BETA2 = 0x3F6666663F666666ULL;  // (0.9f, 0.9f)
    const u64 NEG12 = 0xBF800000BF800000ULL;  // (-1.0f, -1.0f)

    u64 mem[4] = {0ULL, 0ULL, 0ULL, 0ULL};
    u64 rst[4] = {0ULL, 0ULL, 0ULL, 0ULL};   // (mem_{t-1} > TH) as float 0/1 pairs
    u64 cnt[4] = {0ULL, 0ULL, 0ULL, 0ULL};

    __syncthreads();

    // --- main scan: t in [0, 118) with no spike accumulation ---
    #pragma unroll 2
    for (int t = 0; t < TAIL0; ++t) {
        const ulonglong2* p0 = (const ulonglong2*)(&sx0[t][0]);
        const ulonglong2* p1 = (const ulonglong2*)(&sx1[t][0]);
        ulonglong2 q0a = p0[0], q0b = p0[1];
        ulonglong2 q1a = p1[0], q1b = p1[1];
        u64 xq0[4] = {q0a.x, q0a.y, q0b.x, q0b.y};
        u64 xq1[4] = {q1a.x, q1a.y, q1b.x, q1b.y};
        #pragma unroll
        for (int p = 0; p < 4; ++p) {
            u64 c  = fma2(xq0[p], w0d, mul2(xq1[p], w1d));
            mem[p] = fma2(mem[p], BETA2, c);       // beta*mem + c
            mem[p] = fma2(rst[p], NEG12, mem[p]);  // - reset*TH (reset from prev mem)
            rst[p] = gt1_2(mem[p]);                // spike_t == reset_{t+1}
        }
    }
    // --- last 10 steps: also accumulate spikes ---
    #pragma unroll
    for (int t = TAIL0; t < T_STEPS; ++t) {
        const ulonglong2* p0 = (const ulonglong2*)(&sx0[t][0]);
        const ulonglong2* p1 = (const ulonglong2*)(&sx1[t][0]);
        ulonglong2 q0a = p0[0], q0b = p0[1];
        ulonglong2 q1a = p1[0], q1b = p1[1];
        u64 xq0[4] = {q0a.x, q0a.y, q0b.x, q0b.y};
        u64 xq1[4] = {q1a.x, q1a.y, q1b.x, q1b.y};
        #pragma unroll
        for (int p = 0; p < 4; ++p) {
            u64 c  = fma2(xq0[p], w0d, mul2(xq1[p], w1d));
            mem[p] = fma2(mem[p], BETA2, c);
            mem[p] = fma2(rst[p], NEG12, mem[p]);
            rst[p] = gt1_2(mem[p]);
            cnt[p] = add2(cnt[p], rst[p]);         // count spike_t
        }
    }

    // --- scatter spike counts to shared for the output reduction ---
    #pragma unroll
    for (int p = 0; p < 4; ++p) {
        float clo, chi;
        unpk2(cnt[p], clo, chi);
        sspk[2 * p + 0][tid] = clo;
        sspk[2 * p + 1][tid] = chi;
    }
    __syncthreads();

    // --- out[b0+warp][o] = 0.1 * sum_h cnt[warp][h] * W2[o][h] ---
    const int wrp = tid >> 5, lane = tid & 31;
    float s0 = 0.f, s1 = 0.f;
    #pragma unroll
    for (int k = 0; k < H_DIM / 32; ++k) {
        int h  = lane + k * 32;
        float v = sspk[wrp][h];
        s0 = fmaf(v, __ldg(&w2[h]), s0);
        s1 = fmaf(v, __ldg(&w2[H_DIM + h]), s1);
    }
    #pragma unroll
    for (int off = 16; off; off >>= 1) {
        s0 += __shfl_xor_sync(0xffffffffu, s0, off);
        s1 += __shfl_xor_sync(0xffffffffu, s1, off);
    }
    if (lane == 0) {
        out[(b0 + wrp) * 2 + 0] = s0 * 0.1f;
        out[(b0 + wrp) * 2 + 1] = s1 * 0.1f;
    }
}

extern "C" void kernel_launch(void* const* d_in, const int* in_sizes, int n_in,
                              void* d_out, int out_size) {
    const float2* x  = (const float2*)d_in[0];   // [128, 8192, 2] f32
    const float2* W1 = (const float2*)d_in[1];   // [256, 2] f32
    const float*  W2 = (const float*)d_in[2];    // [2, 256] f32
    float* out = (float*)d_out;                  // [8192, 2] f32
    snn_fused_kernel<<<B_TOT / TILE_B, NTH>>>(x, W1, W2, out);
}

// round 2
// speedup vs baseline: 1.0476x; 1.0476x over previous
#include <cuda_runtime.h>
#include <cstdint>

#define T_STEPS 128
#define B_TOT   8192
#define H_DIM   256
#define TILE_B  8
#define NTH     256
#define TAIL0   118   // first of the last 10 steps

typedef unsigned long long u64;

// ---- packed f32x2 helpers (Blackwell; ptxas never emits these from C++) ----
__device__ __forceinline__ u64 pk2(float lo, float hi) {
    u64 r; asm("mov.b64 %0, {%1, %2};" : "=l"(r) : "f"(lo), "f"(hi)); return r;
}
__device__ __forceinline__ void unpk2(u64 v, float& lo, float& hi) {
    asm("mov.b64 {%0, %1}, %2;" : "=f"(lo), "=f"(hi) : "l"(v));
}
__device__ __forceinline__ u64 fma2(u64 a, u64 b, u64 c) {
    u64 d; asm("fma.rn.f32x2 %0, %1, %2, %3;" : "=l"(d) : "l"(a), "l"(b), "l"(c)); return d;
}
__device__ __forceinline__ u64 mul2(u64 a, u64 b) {
    u64 d; asm("mul.rn.f32x2 %0, %1, %2;" : "=l"(d) : "l"(a), "l"(b)); return d;
}
__device__ __forceinline__ u64 add2(u64 a, u64 b) {
    u64 d; asm("add.rn.f32x2 %0, %1, %2;" : "=l"(d) : "l"(a), "l"(b)); return d;
}
// per-half: (m > 1.0f) ? 1.0f : 0.0f   (2 FSET; the movs are register renames)
__device__ __forceinline__ u64 gt1_2(u64 m) {
    u64 r;
    asm("{\n\t"
        ".reg .f32 plo, phi, rl, rh;\n\t"
        "mov.b64 {plo, phi}, %1;\n\t"
        "set.gt.f32.f32 rl, plo, 0f3F800000;\n\t"
        "set.gt.f32.f32 rh, phi, 0f3F800000;\n\t"
        "mov.b64 %0, {rl, rh};\n\t"
        "}" : "=l"(r) : "l"(m));
    return r;
}

__global__ void __launch_bounds__(NTH, 7)
snn_fused_kernel(const float4* __restrict__ x4,   // [T, B/2] quads (x0,x1,x0,x1)
                 const float2* __restrict__ w1p,  // [H] pairs (W1[h][0], W1[h][1])
                 const float*  __restrict__ w2,   // [2, 256]
                 float* __restrict__ out)         // [B, 2]
{
    // sxp[t][p] = {x0(2p), x0(2p+1), x1(2p), x1(2p+1)} : one LDS.128 per pair
    __shared__ __align__(16) float4 sxp[T_STEPS][TILE_B / 2];
    __shared__ float sspk[TILE_B][H_DIM];

    const int tid = threadIdx.x;
    const int b0  = blockIdx.x * TILE_B;

    // --- stage x tile: src float4 = {x0(2p),x1(2p),x0(2p+1),x1(2p+1)} -> swap mids ---
    #pragma unroll
    for (int i = 0; i < (T_STEPS * TILE_B / 2) / NTH; ++i) {
        int idx = tid + i * NTH;                // linear (t, p)
        int t = idx >> 2, p = idx & 3;
        float4 v = x4[(size_t)t * (B_TOT / 2) + (b0 >> 1) + p];
        sxp[t][p] = make_float4(v.x, v.z, v.y, v.w);
    }

    const float2 w  = w1p[tid];
    const u64 w0d   = pk2(w.x, w.x);
    const u64 w1d   = pk2(w.y, w.y);
    const u64 BETA2 = 0x3F6666663F666666ULL;  // (0.9f, 0.9f)
    const u64 NEG12 = 0xBF800000BF800000ULL;  // (-1.0f, -1.0f)

    u64 mem[4] = {0ULL, 0ULL, 0ULL, 0ULL};
    u64 rst[4] = {0ULL, 0ULL, 0ULL, 0ULL};   // (mem_{t-1} > TH) as float 0/1 pairs

    __syncthreads();

    const ulonglong2* __restrict__ xs = (const ulonglong2*)&sxp[0][0];

    // --- main scan: t in [0, 118), no spike accumulation ---
    #pragma unroll 4
    for (int t = 0; t < TAIL0; ++t) {
        #pragma unroll
        for (int p = 0; p < 4; ++p) {
            ulonglong2 q = xs[t * 4 + p];          // .x = x0 pair, .y = x1 pair
            u64 c  = fma2(q.x, w0d, mul2(q.y, w1d));
            mem[p] = fma2(mem[p], BETA2, c);       // beta*mem + c
            mem[p] = fma2(rst[p], NEG12, mem[p]);  // - reset*TH (reset from prev mem)
            rst[p] = gt1_2(mem[p]);                // spike_t == reset_{t+1}
        }
    }

    // --- last 10 steps: also accumulate spikes ---
    u64 cnt[4] = {0ULL, 0ULL, 0ULL, 0ULL};
    #pragma unroll
    for (int t = TAIL0; t < T_STEPS; ++t) {
        #pragma unroll
        for (int p = 0; p < 4; ++p) {
            ulonglong2 q = xs[t * 4 + p];
            u64 c  = fma2(q.x, w0d, mul2(q.y, w1d));
            mem[p] = fma2(mem[p], BETA2, c);
            mem[p] = fma2(rst[p], NEG12, mem[p]);
            rst[p] = gt1_2(mem[p]);
            cnt[p] = add2(cnt[p], rst[p]);         // count spike_t
        }
    }

    // --- scatter spike counts to shared for the output reduction ---
    #pragma unroll
    for (int p = 0; p < 4; ++p) {
        float clo, chi;
        unpk2(cnt[p], clo, chi);
        sspk[2 * p + 0][tid] = clo;
        sspk[2 * p + 1][tid] = chi;
    }
    __syncthreads();

    // --- out[b0+warp][o] = 0.1 * sum_h cnt[warp][h] * W2[o][h] ---
    const int wrp = tid >> 5, lane = tid & 31;
    float s0 = 0.f, s1 = 0.f;
    #pragma unroll
    for (int k = 0; k < H_DIM / 32; ++k) {
        int h  = lane + k * 32;
        float v = sspk[wrp][h];
        s0 = fmaf(v, __ldg(&w2[h]), s0);
        s1 = fmaf(v, __ldg(&w2[H_DIM + h]), s1);
    }
    #pragma unroll
    for (int off = 16; off; off >>= 1) {
        s0 += __shfl_xor_sync(0xffffffffu, s0, off);
        s1 += __shfl_xor_sync(0xffffffffu, s1, off);
    }
    if (lane == 0) {
        out[(b0 + wrp) * 2 + 0] = s0 * 0.1f;
        out[(b0 + wrp) * 2 + 1] = s1 * 0.1f;
    }
}

extern "C" void kernel_launch(void* const* d_in, const int* in_sizes, int n_in,
                              void* d_out, int out_size) {
    const float4*  x  = (const float4*)d_in[0];   // [128, 8192, 2] f32
    const float2*  W1 = (const float2*)d_in[1];   // [256, 2] f32
    const float*   W2 = (const float*)d_in[2];    // [2, 256] f32
    float* out = (float*)d_out;                   // [8192, 2] f32
    snn_fused_kernel<<<B_TOT / TILE_B, NTH>>>(x, W1, W2, out);
}